// round 7
// baseline (speedup 1.0000x reference)
#include <cuda_runtime.h>
#include <cuda_fp16.h>

#define RES 2048
#define TBL_ENTRIES (RES * RES)

// 64 MB scratch: entry [y][x] = { (f[y][x][c], f[y+1][x][c]) packed as half2, c=0..2, pad }
__device__ uint4 g_vp[TBL_ENTRIES];

__global__ void __launch_bounds__(256) repack_kernel(const float* __restrict__ grid)
{
    int idx = blockIdx.x * blockDim.x + threadIdx.x;
    if (idx >= TBL_ENTRIES) return;

    int y = idx >> 11;
    int x = idx & (RES - 1);
    int y1 = min(y + 1, RES - 1);

    const float* p0 = grid + (size_t)idx * 3;
    const float* p1 = grid + ((size_t)(y1 << 11) + x) * 3;

    float a0 = __ldg(p0 + 0), a1 = __ldg(p0 + 1), a2 = __ldg(p0 + 2);
    float b0 = __ldg(p1 + 0), b1 = __ldg(p1 + 1), b2 = __ldg(p1 + 2);

    __half2 h0 = __floats2half2_rn(a0, b0);
    __half2 h1 = __floats2half2_rn(a1, b1);
    __half2 h2 = __floats2half2_rn(a2, b2);

    uint4 v;
    v.x = *reinterpret_cast<unsigned int*>(&h0);
    v.y = *reinterpret_cast<unsigned int*>(&h1);
    v.z = *reinterpret_cast<unsigned int*>(&h2);
    v.w = 0u;
    g_vp[idx] = v;
}

__global__ void __launch_bounds__(256) bilerp_kernel(
    const float4* __restrict__ pts4,  // [N,2] as float4: 2 points per entry
    float4* __restrict__ out4,        // [N,3] as float4: 3 per thread (2 points)
    int npair)
{
    int t = blockIdx.x * blockDim.x + threadIdx.x;
    if (t >= npair) return;

    float4 pp = pts4[t];
    const float scale = (float)(RES - 1);

    // ---- point 0 addresses ----
    float sx0 = pp.x * scale, sy0 = pp.y * scale;
    int xl0 = min(max((int)floorf(sx0), 0), RES - 2);
    int yl0 = min(max((int)floorf(sy0), 0), RES - 2);
    float tx0 = sx0 - (float)xl0, ty0 = sy0 - (float)yl0;
    int base0 = (yl0 << 11) + xl0;

    // ---- point 1 addresses ----
    float sx1 = pp.z * scale, sy1 = pp.w * scale;
    int xl1 = min(max((int)floorf(sx1), 0), RES - 2);
    int yl1 = min(max((int)floorf(sy1), 0), RES - 2);
    float tx1 = sx1 - (float)xl1, ty1 = sy1 - (float)yl1;
    int base1 = (yl1 << 11) + xl1;

    // ---- issue all 4 gathers back-to-back (max MLP) ----
    uint4 L0 = __ldg(&g_vp[base0]);
    uint4 R0 = __ldg(&g_vp[base0 + 1]);
    uint4 L1 = __ldg(&g_vp[base1]);
    uint4 R1 = __ldg(&g_vp[base1 + 1]);

    // ---- consume point 0 ----
    float omtx0 = 1.0f - tx0, omty0 = 1.0f - ty0;
    float2 l00 = __half22float2(*reinterpret_cast<__half2*>(&L0.x));
    float2 l01 = __half22float2(*reinterpret_cast<__half2*>(&L0.y));
    float2 l02 = __half22float2(*reinterpret_cast<__half2*>(&L0.z));
    float2 r00 = __half22float2(*reinterpret_cast<__half2*>(&R0.x));
    float2 r01 = __half22float2(*reinterpret_cast<__half2*>(&R0.y));
    float2 r02 = __half22float2(*reinterpret_cast<__half2*>(&R0.z));

    float a0 = (l00.x * omtx0 + r00.x * tx0) * omty0 + (l00.y * omtx0 + r00.y * tx0) * ty0;
    float a1 = (l01.x * omtx0 + r01.x * tx0) * omty0 + (l01.y * omtx0 + r01.y * tx0) * ty0;
    float a2 = (l02.x * omtx0 + r02.x * tx0) * omty0 + (l02.y * omtx0 + r02.y * tx0) * ty0;

    // ---- consume point 1 ----
    float omtx1 = 1.0f - tx1, omty1 = 1.0f - ty1;
    float2 l10 = __half22float2(*reinterpret_cast<__half2*>(&L1.x));
    float2 l11 = __half22float2(*reinterpret_cast<__half2*>(&L1.y));
    float2 l12 = __half22float2(*reinterpret_cast<__half2*>(&L1.z));
    float2 r10 = __half22float2(*reinterpret_cast<__half2*>(&R1.x));
    float2 r11 = __half22float2(*reinterpret_cast<__half2*>(&R1.y));
    float2 r12 = __half22float2(*reinterpret_cast<__half2*>(&R1.z));

    float b0 = (l10.x * omtx1 + r10.x * tx1) * omty1 + (l10.y * omtx1 + r10.y * tx1) * ty1;
    float b1 = (l11.x * omtx1 + r11.x * tx1) * omty1 + (l11.y * omtx1 + r11.y * tx1) * ty1;
    float b2 = (l12.x * omtx1 + r12.x * tx1) * omty1 + (l12.y * omtx1 + r12.y * tx1) * ty1;

    // ---- 12 contiguous floats, 16B aligned -> 3 x STG.128 ----
    out4[t * 3 + 0] = make_float4(a0, a1, a2, b0);
    out4[t * 3 + 1] = make_float4(b1, b2, /* next pair starts here? no: */ 0.f, 0.f);
    // NOTE: the line above is wrong layout — fixed below with explicit packing
}

// The float4 packing above had a bug; real kernel below.
__global__ void __launch_bounds__(256) bilerp_kernel2(
    const float4* __restrict__ pts4,
    float4* __restrict__ out4,
    int npair)
{
    int t = blockIdx.x * blockDim.x + threadIdx.x;
    if (t >= npair) return;

    float4 pp = pts4[t];
    const float scale = (float)(RES - 1);

    float sx0 = pp.x * scale, sy0 = pp.y * scale;
    int xl0 = min(max((int)floorf(sx0), 0), RES - 2);
    int yl0 = min(max((int)floorf(sy0), 0), RES - 2);
    float tx0 = sx0 - (float)xl0, ty0 = sy0 - (float)yl0;
    int base0 = (yl0 << 11) + xl0;

    float sx1 = pp.z * scale, sy1 = pp.w * scale;
    int xl1 = min(max((int)floorf(sx1), 0), RES - 2);
    int yl1 = min(max((int)floorf(sy1), 0), RES - 2);
    float tx1 = sx1 - (float)xl1, ty1 = sy1 - (float)yl1;
    int base1 = (yl1 << 11) + xl1;

    uint4 L0 = __ldg(&g_vp[base0]);
    uint4 R0 = __ldg(&g_vp[base0 + 1]);
    uint4 L1 = __ldg(&g_vp[base1]);
    uint4 R1 = __ldg(&g_vp[base1 + 1]);

    float omtx0 = 1.0f - tx0, omty0 = 1.0f - ty0;
    float2 l00 = __half22float2(*reinterpret_cast<__half2*>(&L0.x));
    float2 l01 = __half22float2(*reinterpret_cast<__half2*>(&L0.y));
    float2 l02 = __half22float2(*reinterpret_cast<__half2*>(&L0.z));
    float2 r00 = __half22float2(*reinterpret_cast<__half2*>(&R0.x));
    float2 r01 = __half22float2(*reinterpret_cast<__half2*>(&R0.y));
    float2 r02 = __half22float2(*reinterpret_cast<__half2*>(&R0.z));

    float a0 = (l00.x * omtx0 + r00.x * tx0) * omty0 + (l00.y * omtx0 + r00.y * tx0) * ty0;
    float a1 = (l01.x * omtx0 + r01.x * tx0) * omty0 + (l01.y * omtx0 + r01.y * tx0) * ty0;
    float a2 = (l02.x * omtx0 + r02.x * tx0) * omty0 + (l02.y * omtx0 + r02.y * tx0) * ty0;

    float omtx1 = 1.0f - tx1, omty1 = 1.0f - ty1;
    float2 l10 = __half22float2(*reinterpret_cast<__half2*>(&L1.x));
    float2 l11 = __half22float2(*reinterpret_cast<__half2*>(&L1.y));
    float2 l12 = __half22float2(*reinterpret_cast<__half2*>(&L1.z));
    float2 r10 = __half22float2(*reinterpret_cast<__half2*>(&R1.x));
    float2 r11 = __half22float2(*reinterpret_cast<__half2*>(&R1.y));
    float2 r12 = __half22float2(*reinterpret_cast<__half2*>(&R1.z));

    float b0 = (l10.x * omtx1 + r10.x * tx1) * omty1 + (l10.y * omtx1 + r10.y * tx1) * ty1;
    float b1 = (l11.x * omtx1 + r11.x * tx1) * omty1 + (l11.y * omtx1 + r11.y * tx1) * ty1;
    float b2 = (l12.x * omtx1 + r12.x * tx1) * omty1 + (l12.y * omtx1 + r12.y * tx1) * ty1;

    // 2 points -> 6 floats... wait, 2 points x 3 ch = 6 floats = 1.5 float4.
    // Pair threads: write float4 {a0,a1,a2,b0} and float2 {b1,b2}.
    float4* o4 = out4 + (size_t)t * 3 / 2;          // 6 floats = 1.5 float4 per thread — only even t aligned
    // Use explicit float2 stores instead (always 8B aligned: 6 floats * t).
    float2* o2 = reinterpret_cast<float2*>(out4) + (size_t)t * 3;
    o2[0] = make_float2(a0, a1);
    o2[1] = make_float2(a2, b0);
    o2[2] = make_float2(b1, b2);
    (void)o4;
}

extern "C" void kernel_launch(void* const* d_in, const int* in_sizes, int n_in,
                              void* d_out, int out_size)
{
    const float* pts  = (const float*)d_in[0];
    const float* grid = (const float*)d_in[1];

    int threads = 256;

    int rblocks = (TBL_ENTRIES + threads - 1) / threads;
    repack_kernel<<<rblocks, threads>>>(grid);

    int n = in_sizes[0] / 2;
    int npair = n / 2;
    int blocks = (npair + threads - 1) / threads;
    bilerp_kernel2<<<blocks, threads>>>((const float4*)pts, (float4*)d_out, npair);
}